// round 17
// baseline (speedup 1.0000x reference)
#include <cuda_runtime.h>
#include <cstdint>

// Fixed problem shape
#define NB 8
#define IC 16
#define OC 32
#define H  128
#define W  128
#define HP 130
#define TH 2      // output rows per tile
#define TW 64     // output cols per tile
#define NTILES 1024
#define GRID_P 444    // 148 SMs x 3 CTAs

typedef unsigned long long ull;

// Packed (cos S, sin S): [n*IC][HP][W], 17 MB
__device__ ull g_cs[NB * IC * HP * W];

__device__ __forceinline__ void ffma2(ull& d, ull a, ull b) {
    asm("fma.rn.f32x2 %0, %1, %2, %0;" : "+l"(d) : "l"(a), "l"(b));
}

__device__ __forceinline__ ull pack2(float lo, float hi) {
    return (ull)__float_as_uint(lo) | ((ull)__float_as_uint(hi) << 32);
}

// ---------------- Kernel 1: cs tensor, warp-per-row vectorized ----------------
// grid (17, 128): blockIdx.y = nj, warp handles one hp row (4 cols/lane).
__global__ __launch_bounds__(256)
void cs_kernel(const float* __restrict__ x) {
    const int lane = threadIdx.x & 31;
    const int hp   = blockIdx.x * 8 + (threadIdx.x >> 5);
    if (hp >= HP) return;
    const int nj = blockIdx.y;

    ull o0, o1, o2, o3;
    const int gr = hp - 1;
    if ((unsigned)gr < (unsigned)H) {
        float4 v = reinterpret_cast<const float4*>(
            x + ((size_t)nj * H + gr) * W)[lane];
        float lf = __shfl_up_sync(0xffffffffu, v.w, 1);
        if (lane == 0)  lf = 0.f;
        float rt = __shfl_down_sync(0xffffffffu, v.x, 1);
        if (lane == 31) rt = 0.f;
        float s, c;
        __sincosf(lf  + v.x + v.y, &s, &c); o0 = pack2(c, s);
        __sincosf(v.x + v.y + v.z, &s, &c); o1 = pack2(c, s);
        __sincosf(v.y + v.z + v.w, &s, &c); o2 = pack2(c, s);
        __sincosf(v.z + v.w + rt,  &s, &c); o3 = pack2(c, s);
    } else {
        o0 = o1 = o2 = o3 = pack2(1.f, 0.f);   // S = 0 on pad rows
    }
    ull* dst = g_cs + ((size_t)nj * HP + hp) * W + 4 * lane;
    *reinterpret_cast<ulonglong2*>(dst)     = make_ulonglong2(o0, o1);
    *reinterpret_cast<ulonglong2*>(dst + 2) = make_ulonglong2(o2, o3);
}

// ---------------- Kernel 2: persistent chunked contraction ----------------
// 444 CTAs; CTA processes tiles bid, bid+444, bid+888 (<1024). Tile =
// (tw = t&1, hy = (t>>1)&63, n = t>>7): 2 rows x 64 cols x 32 ch.
// Tile split into 4 chunks of 4 j; chunks triple-buffered via cp.async with
// prefetch depth 1; ONE barrier per chunk. Coef computed in-kernel.
__global__ __launch_bounds__(256, 3)
void contract_kernel(const float* __restrict__ theta, float* __restrict__ out) {
    __shared__ __align__(16) ull sBuf[3][4 * 4 * TW];   // 3 x 8 KB
    __shared__ __align__(16) ull sCoef[IC * OC * 3];    // 12 KB

    const int tid  = threadIdx.x;
    const int lane = tid & 31;
    const int ig   = tid >> 5;          // warp = channel group 4*ig..4*ig+3
    const int bid  = blockIdx.x;
    const int w0   = 2 * lane;

    // ---- Coef table in-kernel: 1536 entries, 6 sincosf per thread ----
    #pragma unroll
    for (int u = 0; u < 6; ++u) {
        int e = u * 256 + tid;          // [0,1536): e = ((j*32)+i)*3 + k
        int j = e / 96;
        int rem = e - j * 96;
        int i = rem / 3;
        int k = rem - i * 3;
        float s, c;
        sincosf(theta[(i * j) * 3 + k], &s, &c);
        sCoef[j * 96 + (i >> 2) * 12 + (i & 3) * 3 + k] = pack2(c, -s);
    }

    const int nt  = (bid < NTILES - 2 * GRID_P) ? 3 : 2;   // bid<136 -> 3 tiles
    const int nch = nt * 4;

    // chunk issue: tile t, chunk c (j = 4c..4c+3), buffer b. 2 cp.async/thread.
    auto issue = [&](int t, int c, int b) {
        const int twc = t & 1, hy = (t >> 1) & 63, n = t >> 7;
        const ull* gb = g_cs + (((size_t)n * IC + c * 4) * HP + hy * 2) * W
                        + twc * TW;
        #pragma unroll
        for (int it = 0; it < 2; ++it) {
            int q   = it * 256 + tid;   // 0..511
            int c2  = q & 31;
            int row = q >> 5;           // 0..15
            int r   = row & 3, jj = row >> 2;
            const ull* src = gb + ((size_t)jj * HP + r) * W + 2 * c2;
            unsigned dst = (unsigned)__cvta_generic_to_shared(
                &sBuf[b][(jj * 4 + r) * TW + 2 * c2]);
            asm volatile("cp.async.cg.shared.global [%0], [%1], 16;"
                         :: "r"(dst), "l"(src) : "memory");
        }
        asm volatile("cp.async.commit_group;" ::: "memory");
    };

    ull acc[2][4][2];
    #pragma unroll
    for (int q = 0; q < 2; ++q)
        #pragma unroll
        for (int i = 0; i < 4; ++i) {
            acc[q][i][0] = 0ull;
            acc[q][i][1] = 0ull;
        }

    issue(bid, 0, 0);

    const char* coefBase = reinterpret_cast<const char*>(sCoef) + ig * 96;

    #pragma unroll 1
    for (int g = 0; g < nch; ++g) {
        const int gn = g + 1;
        if (gn < nch)
            issue(bid + (gn >> 2) * GRID_P, gn & 3, gn % 3);
        if (gn < nch)
            asm volatile("cp.async.wait_group 1;" ::: "memory");
        else
            asm volatile("cp.async.wait_group 0;" ::: "memory");
        __syncthreads();   // one barrier per chunk (3 buffers -> no trailing sync)

        const ull* sb = sBuf[g % 3];
        const int  c  = g & 3;

        #pragma unroll
        for (int jj = 0; jj < 4; ++jj) {
            const int j = c * 4 + jj;
            const ull* base = sb + jj * 4 * TW + w0;
            ulonglong2 e0 = *reinterpret_cast<const ulonglong2*>(base + 0 * TW);
            ulonglong2 e1 = *reinterpret_cast<const ulonglong2*>(base + 1 * TW);
            ulonglong2 e2 = *reinterpret_cast<const ulonglong2*>(base + 2 * TW);
            ulonglong2 e3 = *reinterpret_cast<const ulonglong2*>(base + 3 * TW);

            const char* cfb = coefBase + j * 768;
            ulonglong2 p0 = *reinterpret_cast<const ulonglong2*>(cfb + 0);
            ulonglong2 p1 = *reinterpret_cast<const ulonglong2*>(cfb + 16);
            ulonglong2 p2 = *reinterpret_cast<const ulonglong2*>(cfb + 32);
            ulonglong2 p3 = *reinterpret_cast<const ulonglong2*>(cfb + 48);
            ulonglong2 p4 = *reinterpret_cast<const ulonglong2*>(cfb + 64);
            ulonglong2 p5 = *reinterpret_cast<const ulonglong2*>(cfb + 80);

            ull C0[4] = { p0.x, p1.y, p3.x, p4.y };
            ull C1[4] = { p0.y, p2.x, p3.y, p5.x };
            ull C2[4] = { p1.x, p2.y, p4.x, p5.y };

            #pragma unroll
            for (int i = 0; i < 4; ++i) {
                ffma2(acc[0][i][0], e0.x, C0[i]);
                ffma2(acc[0][i][0], e1.x, C1[i]);
                ffma2(acc[0][i][0], e2.x, C2[i]);
                ffma2(acc[0][i][1], e1.x, C0[i]);
                ffma2(acc[0][i][1], e2.x, C1[i]);
                ffma2(acc[0][i][1], e3.x, C2[i]);
                ffma2(acc[1][i][0], e0.y, C0[i]);
                ffma2(acc[1][i][0], e1.y, C1[i]);
                ffma2(acc[1][i][0], e2.y, C2[i]);
                ffma2(acc[1][i][1], e1.y, C0[i]);
                ffma2(acc[1][i][1], e2.y, C1[i]);
                ffma2(acc[1][i][1], e3.y, C2[i]);
            }
        }

        if (c == 3) {
            // Tile epilogue: out = (lo + hi) / 3, STG.64; reset acc
            const int t  = bid + (g >> 2) * GRID_P;
            const int twc = t & 1, hy = (t >> 1) & 63, n = t >> 7;
            const int h0 = hy * 2;
            #pragma unroll
            for (int i = 0; i < 4; ++i) {
                const int ch = ig * 4 + i;
                float* op = out + ((size_t)(n * OC + ch) * H + h0) * W
                            + twc * TW + w0;
                #pragma unroll
                for (int r = 0; r < 2; ++r) {
                    ull ax = acc[0][i][r];
                    ull ay = acc[1][i][r];
                    float2 o;
                    o.x = (__uint_as_float((unsigned)(ax & 0xffffffffu)) +
                           __uint_as_float((unsigned)(ax >> 32))) * (1.0f / 3.0f);
                    o.y = (__uint_as_float((unsigned)(ay & 0xffffffffu)) +
                           __uint_as_float((unsigned)(ay >> 32))) * (1.0f / 3.0f);
                    *reinterpret_cast<float2*>(op + (size_t)r * W) = o;
                    acc[0][i][r] = 0ull;
                    acc[1][i][r] = 0ull;
                }
            }
        }
    }
}

extern "C" void kernel_launch(void* const* d_in, const int* in_sizes, int n_in,
                              void* d_out, int out_size) {
    const float* x     = (const float*)d_in[0];   // (8,16,128,128) f32
    const float* theta = (const float*)d_in[1];   // (1536,3) f32
    float* out = (float*)d_out;                   // (8,32,128,128) f32

    dim3 pgrid((HP + 7) / 8, NB * IC);            // (17, 128)
    cs_kernel<<<pgrid, 256>>>(x);

    contract_kernel<<<GRID_P, 256>>>(theta, out);
}